// round 6
// baseline (speedup 1.0000x reference)
#include <cuda_runtime.h>
#include <math.h>

#define Bb 2
#define Nn 4096
#define NT (Bb*Nn)
#define Kk 32
#define D0 64
#define E2C 322
#define W1P 384
#define H1P 324
#define MSP 36
#define G1P 136
#define ASZ 4224

typedef unsigned long long ull;

__device__ float PI_g[(size_t)NT * E2C + 384];
__device__ float PJ_g[(size_t)NT * E2C + 384];

__device__ __forceinline__ float siluf(float x) { return x / (1.f + __expf(-x)); }
__device__ __forceinline__ float sigmf(float x) { return 1.f / (1.f + __expf(-x)); }
__device__ __forceinline__ ull pack2(float lo, float hi) {
    ull r; asm("mov.b64 %0, {%1, %2};" : "=l"(r) : "f"(lo), "f"(hi)); return r;
}
__device__ __forceinline__ void unpack2(ull v, float& lo, float& hi) {
    asm("mov.b64 {%0, %1}, %2;" : "=f"(lo), "=f"(hi) : "l"(v));
}
__device__ __forceinline__ ull ffma2(ull a, ull b, ull c) {
    ull d; asm("fma.rn.f32x2 %0, %1, %2, %3;" : "=l"(d) : "l"(a), "l"(b), "l"(c)); return d;
}

// ---------------- per-node projections: PI = nodes @ We1[0:64] + be1, PJ = nodes @ We1[64:128]
__global__ void __launch_bounds__(256)
proj_kernel(const float* __restrict__ f0, const float* __restrict__ We1,
            const float* __restrict__ be1)
{
    __shared__ float nd[16][65];
    const int nb = blockIdx.x * 16;
    const int tid = threadIdx.x;
    for (int idx = tid; idx < 16 * 64; idx += 256)
        nd[idx >> 6][idx & 63] = f0[(size_t)nb * 64 + idx];
    __syncthreads();
    for (int idx = tid; idx < 16 * 161; idx += 256) {
        const int n = idx / 161;
        const int c0 = (idx - n * 161) * 2;
        ull si = 0ull, sj = 0ull;
        #pragma unroll 8
        for (int d = 0; d < 64; d++) {
            const float v = nd[n][d];
            const ull vv = pack2(v, v);
            const float2 wi = __ldg((const float2*)&We1[(size_t)d * E2C + c0]);
            const float2 wj = __ldg((const float2*)&We1[(size_t)(64 + d) * E2C + c0]);
            si = ffma2(vv, pack2(wi.x, wi.y), si);
            sj = ffma2(vv, pack2(wj.x, wj.y), sj);
        }
        float a, b; unpack2(si, a, b);
        float c, d2; unpack2(sj, c, d2);
        *(float2*)&PI_g[(size_t)(nb + n) * E2C + c0] = make_float2(a + be1[c0], b + be1[c0 + 1]);
        *(float2*)&PJ_g[(size_t)(nb + n) * E2C + c0] = make_float2(c, d2);
    }
}

// ---------------- main fused kernel: one block per node, ~70KB smem -> 3 blocks/SM
__global__ void __launch_bounds__(256)
egnn_main(const float* __restrict__ f0, const float* __restrict__ f1,
          const int* __restrict__ nbr, const unsigned char* __restrict__ msk,
          const float* __restrict__ rdist,
          const float* __restrict__ We1,
          const float* __restrict__ We2, const float* __restrict__ be2,
          const float* __restrict__ Wh1, const float* __restrict__ bh1,
          const float* __restrict__ Wh2, const float* __restrict__ bh2,
          const float* __restrict__ Wn1, const float* __restrict__ bn1,
          const float* __restrict__ Wn2, const float* __restrict__ bn2,
          const float* __restrict__ Wg,  const float* __restrict__ bg,
          const float* __restrict__ lng, const float* __restrict__ lnb,
          const float* __restrict__ hns, const float* __restrict__ hnb,
          float* __restrict__ out)
{
    extern __shared__ float sm[];
    float* A       = sm;                       // ASZ: rotating weight stage
    float* H1      = A + ASZ;                  // [32][324]; later aliased by G1 [32][136]
    float* EIc     = H1 + 32 * H1P;            // [32][36]
    float* PI      = EIc + 32 * MSP;           // [384]
    float* MS      = PI + W1P;                 // [32][36]; later aliased by WS
    float* HT2     = MS + 32 * MSP;            // [192]
    float* nodes_s = HT2 + 192;                // [64]
    float* f1i_s   = nodes_s + 64;             // [96]
    float* MI      = f1i_s + 96;               // [32]
    float* NI      = MI + 32;                  // [96]
    float* N1s     = NI + 96;                  // [128]
    float* nouts   = N1s + 128;                // [64]
    float* gates   = nouts + 64;               // [32]
    float* maskv   = gates + 32;               // [32]
    float* stats   = maskv + 32;               // [2]
    int*   nbr_s   = (int*)(stats + 2);        // [32]
    float* G1      = H1;                       // alias (H1 dead after GEMM2)
    float* WS      = MS;                       // alias (MS dead after GEMM3+MI)

    const int tid  = threadIdx.x;
    const int lane = tid & 31;
    const int wrow = tid >> 5;
    const int node = blockIdx.x;
    const int bbase = (node / Nn) * Nn;

    // ---- init: node-i features, per-edge scalars, PI, GEMM1 weight stage 0 ----
    if (tid < 64)           nodes_s[tid]    = f0[(size_t)node * 64 + tid];
    else if (tid < 160)     f1i_s[tid - 64] = f1[(size_t)node * 96 + (tid - 64)];
    if (tid < 32)           nbr_s[tid] = nbr[node * Kk + tid];
    else if (tid < 64)      maskv[tid - 32] = (float)msk[node * Kk + tid - 32];
    else if (tid < 96)      EIc[(tid - 64) * MSP + 32] = rdist[node * Kk + tid - 64];
    for (int c = tid; c < W1P; c += 256)
        PI[c] = (c < E2C) ? PI_g[(size_t)node * E2C + c] : 0.f;
    for (int idx = tid; idx < 11 * W1P; idx += 256) {
        const int r = idx / W1P, c = idx - r * W1P;
        A[idx] = (c < E2C) ? __ldg(&We1[(size_t)(128 + r) * E2C + c]) : 0.f;
    }
    __syncthreads();

    // ---- rel_norm gather + LN stats ----
    #pragma unroll
    for (int i = 0; i < 4; i++) {
        const int e = wrow + 8 * i;
        const float* f1j = f1 + (size_t)(bbase + nbr_s[e]) * 96;
        const float r0 = f1i_s[lane * 3 + 0] - f1j[lane * 3 + 0];
        const float r1 = f1i_s[lane * 3 + 1] - f1j[lane * 3 + 1];
        const float r2 = f1i_s[lane * 3 + 2] - f1j[lane * 3 + 2];
        EIc[e * MSP + lane] = sqrtf(r0 * r0 + r1 * r1 + r2 * r2);
    }
    if (wrow == 7) {
        float x0 = nodes_s[lane], x1 = nodes_s[lane + 32];
        float s = x0 + x1, ss = x0 * x0 + x1 * x1;
        #pragma unroll
        for (int o = 16; o > 0; o >>= 1) {
            s  += __shfl_down_sync(0xffffffffu, s,  o);
            ss += __shfl_down_sync(0xffffffffu, ss, o);
        }
        if (lane == 0) {
            const float mu  = s * (1.f / 64.f);
            const float var = ss * (1.f / 64.f) - mu * mu;
            stats[0] = mu;
            stats[1] = rsqrtf(var + 1e-5f);
        }
    }
    __syncthreads();

    // ---- GEMM1 (K=33, 3 staged chunks, f32x2 over column pairs) ----
    ull acc2[4][6];
    #pragma unroll
    for (int i = 0; i < 4; i++)
        #pragma unroll
        for (int jj = 0; jj < 6; jj++) acc2[i][jj] = 0ull;

    #pragma unroll
    for (int s = 0; s < 3; s++) {
        const int k0 = 11 * s;
        for (int kr = 0; kr < 11; kr++) {
            const int k = k0 + kr;
            ull ev[4];
            #pragma unroll
            for (int i = 0; i < 4; i++) {
                const float e = EIc[(wrow + 8 * i) * MSP + k];
                ev[i] = pack2(e, e);
            }
            #pragma unroll
            for (int jj = 0; jj < 6; jj++) {
                const ull wv = *(const ull*)&A[kr * W1P + ((lane + 32 * jj) << 1)];
                acc2[0][jj] = ffma2(ev[0], wv, acc2[0][jj]);
                acc2[1][jj] = ffma2(ev[1], wv, acc2[1][jj]);
                acc2[2][jj] = ffma2(ev[2], wv, acc2[2][jj]);
                acc2[3][jj] = ffma2(ev[3], wv, acc2[3][jj]);
            }
        }
        __syncthreads();
        if (s < 2) {
            for (int idx = tid; idx < 11 * W1P; idx += 256) {
                const int r = idx / W1P, c = idx - r * W1P;
                A[idx] = (c < E2C) ? __ldg(&We1[(size_t)(128 + 11 * (s + 1) + r) * E2C + c]) : 0.f;
            }
            __syncthreads();
        }
    }

    // ---- epilogue (PI + PJ gather + silu -> H1), overlapped with interleaved We2 stage 0 ----
    #pragma unroll
    for (int i = 0; i < 4; i++) {
        const int e = wrow + 8 * i;
        const float* pj = PJ_g + (size_t)(bbase + nbr_s[e]) * E2C;
        #pragma unroll
        for (int jj = 0; jj < 6; jj++) {
            const int c0 = (lane + 32 * jj) << 1;
            if (c0 < E2C) {
                float lo, hi; unpack2(acc2[i][jj], lo, hi);
                const float2 pi2 = *(const float2*)&PI[c0];
                const float2 pj2 = __ldg((const float2*)(pj + c0));
                float2 o;
                o.x = siluf(lo + pi2.x + pj2.x);
                o.y = siluf(hi + pi2.y + pj2.y);
                *(float2*)&H1[e * H1P + c0] = o;
            }
        }
    }
    if (tid < 32) *(float2*)&H1[tid * H1P + E2C] = make_float2(0.f, 0.f);  // zero K-pad
    // stage We2 quads 0..31 interleaved: AI[q*128 + l*4 + m] = We2[(4q+m)*32 + l]
    for (int idx = tid; idx < 32 * 32; idx += 256) {
        const int q = idx >> 5, l = idx & 31;
        #pragma unroll
        for (int m = 0; m < 4; m++)
            A[q * 128 + l * 4 + m] = __ldg(&We2[(4 * q + m) * 32 + l]);
    }
    __syncthreads();

    // ---- GEMM2 (K=324, f32x2 packed over K, 3 staged chunks of 32/32/17 quads) ----
    {
        ull a2[4] = {0ull, 0ull, 0ull, 0ull};
        #pragma unroll
        for (int s = 0; s < 3; s++) {
            const int nq = (s < 2) ? 32 : 17;
            const int r0 = s * 128;
            for (int q = 0; q < nq; q++) {
                const ull w01 = *(const ull*)&A[q * 128 + lane * 4];
                const ull w23 = *(const ull*)&A[q * 128 + lane * 4 + 2];
                #pragma unroll
                for (int i = 0; i < 4; i++) {
                    const float* hrow = &H1[(wrow + 8 * i) * H1P + r0 + 4 * q];
                    a2[i] = ffma2(*(const ull*)hrow, w01, a2[i]);
                    a2[i] = ffma2(*(const ull*)(hrow + 2), w23, a2[i]);
                }
            }
            __syncthreads();
            if (s < 2) {
                const int nn = (s == 0) ? 32 : 17;
                const int rb = (s + 1) * 128;
                for (int idx = tid; idx < nn * 32; idx += 256) {
                    const int q = idx >> 5, l = idx & 31;
                    #pragma unroll
                    for (int m = 0; m < 4; m++) {
                        const int r = rb + 4 * q + m;
                        A[q * 128 + l * 4 + m] = (r < E2C) ? __ldg(&We2[r * 32 + l]) : 0.f;
                    }
                }
                __syncthreads();
            }
        }
        #pragma unroll
        for (int i = 0; i < 4; i++) {
            float lo, hi; unpack2(a2[i], lo, hi);
            MS[(wrow + 8 * i) * MSP + lane] = siluf(lo + hi + be2[lane]);
        }
    }
    __syncthreads();

    // ---- stage Wh1 plain (warps 0-6) + MI from MS (warp 7) ----
    if (wrow < 7) {
        const float4* src = (const float4*)Wh1;
        float4* dst = (float4*)A;
        for (int idx = tid; idx < 1024; idx += 224)
            dst[idx] = __ldg(&src[idx]);
    } else {
        float s = 0.f;
        #pragma unroll 8
        for (int e = 0; e < 32; e++)
            s += maskv[e] * MS[e * MSP + lane];
        MI[lane] = s;
    }
    __syncthreads();

    // ---- GEMM3: G1[32][128] = silu(MS @ Wh1s + bh1)  (f32x2 over column pairs) ----
    ull a3[4][2];
    #pragma unroll
    for (int i = 0; i < 4; i++) { a3[i][0] = 0ull; a3[i][1] = 0ull; }
    #pragma unroll 4
    for (int r = 0; r < 32; r++) {
        ull mv[4];
        #pragma unroll
        for (int i = 0; i < 4; i++) {
            const float m = MS[(wrow + 8 * i) * MSP + r];
            mv[i] = pack2(m, m);
        }
        #pragma unroll
        for (int jj = 0; jj < 2; jj++) {
            const ull wv = *(const ull*)&A[r * 128 + ((lane + 32 * jj) << 1)];
            a3[0][jj] = ffma2(mv[0], wv, a3[0][jj]);
            a3[1][jj] = ffma2(mv[1], wv, a3[1][jj]);
            a3[2][jj] = ffma2(mv[2], wv, a3[2][jj]);
            a3[3][jj] = ffma2(mv[3], wv, a3[3][jj]);
        }
    }
    __syncthreads();   // MS reads done (WS will alias), A (Wh1) reads done
    #pragma unroll
    for (int i = 0; i < 4; i++)
        #pragma unroll
        for (int jj = 0; jj < 2; jj++) {
            const int c0 = (lane + 32 * jj) << 1;
            float lo, hi; unpack2(a3[i][jj], lo, hi);
            float2 o;
            o.x = siluf(lo + bh1[c0]);
            o.y = siluf(hi + bh1[c0 + 1]);
            *(float2*)&G1[(wrow + 8 * i) * G1P + c0] = o;
        }
    // stage Wh2 interleaved into A (32 quads)
    for (int idx = tid; idx < 32 * 32; idx += 256) {
        const int q = idx >> 5, l = idx & 31;
        #pragma unroll
        for (int m = 0; m < 4; m++)
            A[q * 128 + l * 4 + m] = __ldg(&Wh2[(4 * q + m) * 32 + l]);
    }
    __syncthreads();

    // ---- GEMM4: WS[32][32] = G1 @ Wh2s + bh2  (f32x2 over K, WS aliases MS) ----
    {
        ull a4[4] = {0ull, 0ull, 0ull, 0ull};
        for (int q = 0; q < 32; q++) {
            const ull w01 = *(const ull*)&A[q * 128 + lane * 4];
            const ull w23 = *(const ull*)&A[q * 128 + lane * 4 + 2];
            #pragma unroll
            for (int i = 0; i < 4; i++) {
                const float* grow = &G1[(wrow + 8 * i) * G1P + 4 * q];
                a4[i] = ffma2(*(const ull*)grow, w01, a4[i]);
                a4[i] = ffma2(*(const ull*)(grow + 2), w23, a4[i]);
            }
        }
        #pragma unroll
        for (int i = 0; i < 4; i++) {
            float lo, hi; unpack2(a4[i], lo, hi);
            WS[(wrow + 8 * i) * MSP + lane] = lo + hi + bh2[lane];
        }
    }
    __syncthreads();

    // ---- htype_update (warps 0-5, two e-halves), NI prep (warps 6-7) ----
    if (tid < 192) {
        const int half = (tid >= 96);
        const int t = tid - 96 * half;
        const int d = t / 3;
        const float hs = hns[d], hb = hnb[d];
        const float fi = f1i_s[t];
        const int e0 = half * 16;
        float s = 0.f;
        #pragma unroll 4
        for (int e = e0; e < e0 + 16; e++) {
            const float nrm  = EIc[e * MSP + d];
            const float coef = __fdividef(nrm * hs + hb, fmaxf(nrm, 1e-8f));
            const float relv = fi - __ldg(&f1[(size_t)(bbase + nbr_s[e]) * 96 + t]);
            s += relv * coef * WS[e * MSP + d];
        }
        HT2[tid] = s;
    } else if (tid < 192 + 64) {
        const int c = tid - 192;
        NI[c] = (nodes_s[c] - stats[0]) * stats[1] * lng[c] + lnb[c];
        if (c < 32) NI[64 + c] = MI[c];
    }
    __syncthreads();

    // ---- N1[128] = silu(node_in @ Wn1 + bn1) ----
    if (tid < 128) {
        float a = 0.f;
        #pragma unroll 8
        for (int r = 0; r < 96; r++) a += NI[r] * __ldg(&Wn1[r * 128 + tid]);
        N1s[tid] = siluf(a + bn1[tid]);
    }
    __syncthreads();

    // ---- node_out[64] = N1 @ Wn2 + bn2 + nodes ----
    if (tid < 64) {
        float a = 0.f;
        #pragma unroll 8
        for (int r = 0; r < 128; r++) a += N1s[r] * __ldg(&Wn2[r * 64 + tid]);
        const float v = a + bn2[tid] + nodes_s[tid];
        nouts[tid] = v;
        out[(size_t)node * 64 + tid] = v;
    }
    __syncthreads();

    // ---- gate[32] = sigmoid(node_out @ Wg + bg) ----
    if (tid < 32) {
        float a = 0.f;
        #pragma unroll 8
        for (int r = 0; r < 64; r++) a += nouts[r] * __ldg(&Wg[r * 32 + tid]);
        gates[tid] = sigmf(a + bg[tid]);
    }
    __syncthreads();

    // ---- f1_out = (features1 + htype_update) * gate ----
    if (tid < 96) {
        const int d = tid / 3;
        const float v = (f1i_s[tid] + HT2[tid] + HT2[96 + tid]) * gates[d];
        out[(size_t)Bb * Nn * D0 + (size_t)node * 96 + tid] = v;
    }
}

extern "C" void kernel_launch(void* const* d_in, const int* in_sizes, int n_in,
                              void* d_out, int out_size) {
    const float* f0   = (const float*)d_in[0];
    const float* f1   = (const float*)d_in[1];
    const int*   nbr  = (const int*)d_in[2];
    const unsigned char* msk = (const unsigned char*)d_in[3];
    const float* rdist= (const float*)d_in[4];
    const float* We1  = (const float*)d_in[5];
    const float* be1  = (const float*)d_in[6];
    const float* We2  = (const float*)d_in[7];
    const float* be2  = (const float*)d_in[8];
    const float* Wh1  = (const float*)d_in[9];
    const float* bh1  = (const float*)d_in[10];
    const float* Wh2  = (const float*)d_in[11];
    const float* bh2  = (const float*)d_in[12];
    const float* Wn1  = (const float*)d_in[13];
    const float* bn1  = (const float*)d_in[14];
    const float* Wn2  = (const float*)d_in[15];
    const float* bn2  = (const float*)d_in[16];
    const float* Wg   = (const float*)d_in[17];
    const float* bg   = (const float*)d_in[18];
    const float* lng  = (const float*)d_in[19];
    const float* lnb  = (const float*)d_in[20];
    const float* hns  = (const float*)d_in[21];
    const float* hnb  = (const float*)d_in[22];
    float* out = (float*)d_out;

    proj_kernel<<<NT / 16, 256>>>(f0, We1, be1);

    const size_t smem_floats =
        (size_t)ASZ + 32 * H1P + 32 * MSP + W1P + 32 * MSP + 192 +
        64 + 96 + 32 + 96 + 128 + 64 + 32 + 32 + 2 + 32;
    const size_t smem_bytes = smem_floats * sizeof(float);

    cudaFuncSetAttribute(egnn_main, cudaFuncAttributeMaxDynamicSharedMemorySize,
                         (int)smem_bytes);

    egnn_main<<<NT, 256, smem_bytes>>>(
        f0, f1, nbr, msk, rdist, We1,
        We2, be2, Wh1, bh1, Wh2, bh2,
        Wn1, bn1, Wn2, bn2, Wg, bg, lng, lnb, hns, hnb, out);
}

// round 7
// speedup vs baseline: 1.7524x; 1.7524x over previous
#include <cuda_runtime.h>
#include <math.h>

#define Bb 2
#define Nn 4096
#define NT (Bb*Nn)
#define Kk 32
#define D0 64
#define E2C 322

__device__ float PI_g[(size_t)NT * E2C + 384];
__device__ float PJ_g[(size_t)NT * E2C + 384];

__device__ __forceinline__ float siluf(float x) { return x / (1.f + __expf(-x)); }
__device__ __forceinline__ float sigmf(float x) { return 1.f / (1.f + __expf(-x)); }
// pack two fp32 -> bf16x2 (lo in bits[0:16))
__device__ __forceinline__ unsigned bf2(float lo, float hi) {
    unsigned r; asm("cvt.rn.bf16x2.f32 %0, %1, %2;" : "=r"(r) : "f"(hi), "f"(lo)); return r;
}
__device__ __forceinline__ unsigned bfsplat(float x) {
    unsigned r; asm("cvt.rn.bf16x2.f32 %0, %1, %1;" : "=r"(r) : "f"(x)); return r;
}
__device__ __forceinline__ unsigned hfma2(unsigned a, unsigned b, unsigned c) {
    unsigned d; asm("fma.rn.bf16x2 %0, %1, %2, %3;" : "=r"(d) : "r"(a), "r"(b), "r"(c)); return d;
}
__device__ __forceinline__ float blo(unsigned u) { return __uint_as_float(u << 16); }
__device__ __forceinline__ float bhi(unsigned u) { return __uint_as_float(u & 0xffff0000u); }

// ---------------- per-node projections (fp32): PI = nodes @ We1[0:64] + be1, PJ = nodes @ We1[64:128]
__global__ void __launch_bounds__(256)
proj_kernel(const float* __restrict__ f0, const float* __restrict__ We1,
            const float* __restrict__ be1)
{
    __shared__ float nd[16][65];
    const int nb = blockIdx.x * 16;
    const int tid = threadIdx.x;
    for (int idx = tid; idx < 16 * 64; idx += 256)
        nd[idx >> 6][idx & 63] = f0[(size_t)nb * 64 + idx];
    __syncthreads();
    for (int idx = tid; idx < 16 * E2C; idx += 256) {
        const int n = idx / E2C;
        const int c = idx - n * E2C;
        float si = 0.f, sj = 0.f;
        #pragma unroll 8
        for (int d = 0; d < 64; d++) {
            const float v = nd[n][d];
            si += v * __ldg(&We1[d * E2C + c]);
            sj += v * __ldg(&We1[(64 + d) * E2C + c]);
        }
        PI_g[(size_t)(nb + n) * E2C + c] = si + be1[c];
        PJ_g[(size_t)(nb + n) * E2C + c] = sj;
    }
}

// ---------------- main fused kernel: bf16x2 edge GEMMs, ~53KB smem -> 4 blocks/SM
__global__ void __launch_bounds__(256, 4)
egnn_main(const float* __restrict__ f0, const float* __restrict__ f1,
          const int* __restrict__ nbr, const unsigned char* __restrict__ msk,
          const float* __restrict__ rdist,
          const float* __restrict__ We1,
          const float* __restrict__ We2, const float* __restrict__ be2,
          const float* __restrict__ Wh1, const float* __restrict__ bh1,
          const float* __restrict__ Wh2, const float* __restrict__ bh2,
          const float* __restrict__ Wn1, const float* __restrict__ bn1,
          const float* __restrict__ Wn2, const float* __restrict__ bn2,
          const float* __restrict__ Wg,  const float* __restrict__ bg,
          const float* __restrict__ lng, const float* __restrict__ lnb,
          const float* __restrict__ hns, const float* __restrict__ hnb,
          float* __restrict__ out)
{
    extern __shared__ float sm[];
    unsigned* A    = (unsigned*)sm;            // 2688 u32: rotating bf16 weight stage
    unsigned* H1u  = A + 2688;                 // 32 x 164 u32 (bf16 pairs); later aliased by G1u
    float*    EIc  = (float*)(H1u + 5248);     // [32][36] rel_norm fp32
    unsigned* EIb  = (unsigned*)(EIc + 32*36); // [32][36] splat bf16x2 (k=0..31 relnorm, 32 rdist)
    float*    PI   = (float*)(EIb + 32*36);    // [324]
    unsigned* MSb  = (unsigned*)(PI + 324);    // [32][36] m_ij splat bf16x2
    float*    WS   = (float*)(MSb + 32*36);    // [32][36] w fp32
    float*    HT2  = WS + 32*36;               // [192]
    float*    nodes_s = HT2 + 192;             // [64]
    float*    f1i_s   = nodes_s + 64;          // [96]
    float*    MI   = f1i_s + 96;               // [32]
    float*    NI   = MI + 32;                  // [96]
    float*    N1s  = NI + 96;                  // [128]
    float*    nouts= N1s + 128;                // [64]
    float*    gates= nouts + 64;               // [32]
    float*    maskv= gates + 32;               // [32]
    float*    stats= maskv + 32;               // [2]
    int*      nbr_s= (int*)(stats + 2);        // [32]
    unsigned* G1u  = H1u;                      // alias: [32][68] u32

    const int tid  = threadIdx.x;
    const int lane = tid & 31;
    const int wrow = tid >> 5;
    const int node = blockIdx.x;
    const int bbase = (node / Nn) * Nn;

    // ---- P0: node features, per-edge scalars, PI, GEMM1 weight stage 0 ----
    if (tid < 64)           nodes_s[tid]    = f0[(size_t)node * 64 + tid];
    else if (tid < 160)     f1i_s[tid - 64] = f1[(size_t)node * 96 + (tid - 64)];
    if (tid < 32)           nbr_s[tid] = nbr[node * Kk + tid];
    else if (tid < 64)      maskv[tid - 32] = (float)msk[node * Kk + tid - 32];
    else if (tid < 96)      EIb[(tid - 64) * 36 + 32] = bfsplat(rdist[node * Kk + tid - 64]);
    for (int c = tid; c < 324; c += 256)
        PI[c] = (c < E2C) ? PI_g[(size_t)node * E2C + c] : 0.f;
    for (int idx = tid; idx < 11 * 192; idx += 256) {
        const int kr = idx / 192, p = idx - kr * 192;
        unsigned v = 0u;
        if (p < 161) {
            const float2 w = __ldg((const float2*)&We1[(size_t)(128 + kr) * E2C + 2 * p]);
            v = bf2(w.x, w.y);
        }
        A[idx] = v;
    }
    __syncthreads();

    // ---- P1: rel_norm gather + LN stats ----
    #pragma unroll
    for (int i = 0; i < 4; i++) {
        const int e = wrow + 8 * i;
        const float* f1j = f1 + (size_t)(bbase + nbr_s[e]) * 96;
        const float r0 = f1i_s[lane * 3 + 0] - f1j[lane * 3 + 0];
        const float r1 = f1i_s[lane * 3 + 1] - f1j[lane * 3 + 1];
        const float r2 = f1i_s[lane * 3 + 2] - f1j[lane * 3 + 2];
        const float nrm = sqrtf(r0 * r0 + r1 * r1 + r2 * r2);
        EIc[e * 36 + lane] = nrm;
        EIb[e * 36 + lane] = bfsplat(nrm);
    }
    if (wrow == 7) {
        float x0 = nodes_s[lane], x1 = nodes_s[lane + 32];
        float s = x0 + x1, ss = x0 * x0 + x1 * x1;
        #pragma unroll
        for (int o = 16; o > 0; o >>= 1) {
            s  += __shfl_down_sync(0xffffffffu, s,  o);
            ss += __shfl_down_sync(0xffffffffu, ss, o);
        }
        if (lane == 0) {
            const float mu  = s * (1.f / 64.f);
            const float var = ss * (1.f / 64.f) - mu * mu;
            stats[0] = mu;
            stats[1] = rsqrtf(var + 1e-5f);
        }
    }
    __syncthreads();

    // ---- GEMM1 (K=33, 3 staged chunks of 11 rows, bf16x2 over column pairs) ----
    unsigned acc2[4][6];
    #pragma unroll
    for (int i = 0; i < 4; i++)
        #pragma unroll
        for (int jj = 0; jj < 6; jj++) acc2[i][jj] = 0u;

    #pragma unroll
    for (int s = 0; s < 3; s++) {
        for (int kr = 0; kr < 11; kr++) {
            const int k = 11 * s + kr;
            unsigned ev[4];
            #pragma unroll
            for (int i = 0; i < 4; i++) ev[i] = EIb[(wrow + 8 * i) * 36 + k];
            #pragma unroll
            for (int jj = 0; jj < 6; jj++) {
                const unsigned w = A[kr * 192 + lane + 32 * jj];
                acc2[0][jj] = hfma2(ev[0], w, acc2[0][jj]);
                acc2[1][jj] = hfma2(ev[1], w, acc2[1][jj]);
                acc2[2][jj] = hfma2(ev[2], w, acc2[2][jj]);
                acc2[3][jj] = hfma2(ev[3], w, acc2[3][jj]);
            }
        }
        __syncthreads();
        if (s < 2) {
            for (int idx = tid; idx < 11 * 192; idx += 256) {
                const int kr = idx / 192, p = idx - kr * 192;
                unsigned v = 0u;
                if (p < 161) {
                    const float2 w = __ldg((const float2*)&We1[(size_t)(128 + 11 * (s + 1) + kr) * E2C + 2 * p]);
                    v = bf2(w.x, w.y);
                }
                A[idx] = v;
            }
            __syncthreads();
        }
    }

    // ---- epilogue: H1 = bf16(silu(acc + PI + PJ)), overlapped with We2 chunk-0 staging ----
    #pragma unroll
    for (int i = 0; i < 4; i++) {
        const int e = wrow + 8 * i;
        const float* pj = PJ_g + (size_t)(bbase + nbr_s[e]) * E2C;
        #pragma unroll
        for (int jj = 0; jj < 6; jj++) {
            const int p = lane + 32 * jj;
            if (p < 161) {
                const float2 pi2 = *(const float2*)&PI[2 * p];
                const float2 pj2 = __ldg((const float2*)(pj + 2 * p));
                const float h0 = siluf(blo(acc2[i][jj]) + pi2.x + pj2.x);
                const float h1 = siluf(bhi(acc2[i][jj]) + pi2.y + pj2.y);
                H1u[e * 164 + p] = bf2(h0, h1);
            }
        }
    }
    if (tid < 96) H1u[(tid / 3) * 164 + 161 + (tid % 3)] = 0u;   // zero K-pad (cols 322..327)
    // stage We2 chunks cg 0..20 interleaved bf16 pairs over K
    for (int idx = tid; idx < 21 * 32; idx += 256) {
        const int c8 = idx >> 5, l = idx & 31;
        #pragma unroll
        for (int m = 0; m < 4; m++) {
            const int k = 8 * c8 + 2 * m;
            const float w0 = __ldg(&We2[k * 32 + l]);
            const float w1 = __ldg(&We2[(k + 1) * 32 + l]);
            A[c8 * 128 + l * 4 + m] = bf2(w0, w1);
        }
    }
    __syncthreads();

    // ---- GEMM2 (K=328 incl pad, bf16x2 over K, 2 staged chunks: 21 + 20 8-col groups) ----
    {
        unsigned a2[4] = {0u, 0u, 0u, 0u};
        const uint4* A4 = (const uint4*)A;
        const uint4* H4 = (const uint4*)H1u;   // row stride 41 uint4
        for (int c = 0; c < 21; c++) {
            const uint4 w = A4[c * 32 + lane];
            #pragma unroll
            for (int i = 0; i < 4; i++) {
                const uint4 h = H4[(wrow + 8 * i) * 41 + c];
                a2[i] = hfma2(h.x, w.x, a2[i]);
                a2[i] = hfma2(h.y, w.y, a2[i]);
                a2[i] = hfma2(h.z, w.z, a2[i]);
                a2[i] = hfma2(h.w, w.w, a2[i]);
            }
        }
        __syncthreads();
        for (int idx = tid; idx < 20 * 32; idx += 256) {
            const int c8 = idx >> 5, l = idx & 31;
            #pragma unroll
            for (int m = 0; m < 4; m++) {
                const int k = 8 * (21 + c8) + 2 * m;
                const float w0 = (k     < E2C) ? __ldg(&We2[k * 32 + l])       : 0.f;
                const float w1 = (k + 1 < E2C) ? __ldg(&We2[(k + 1) * 32 + l]) : 0.f;
                A[c8 * 128 + l * 4 + m] = bf2(w0, w1);
            }
        }
        __syncthreads();
        for (int c = 0; c < 20; c++) {
            const uint4 w = A4[c * 32 + lane];
            #pragma unroll
            for (int i = 0; i < 4; i++) {
                const uint4 h = H4[(wrow + 8 * i) * 41 + 21 + c];
                a2[i] = hfma2(h.x, w.x, a2[i]);
                a2[i] = hfma2(h.y, w.y, a2[i]);
                a2[i] = hfma2(h.z, w.z, a2[i]);
                a2[i] = hfma2(h.w, w.w, a2[i]);
            }
        }
        #pragma unroll
        for (int i = 0; i < 4; i++) {
            const float m = siluf(blo(a2[i]) + bhi(a2[i]) + be2[lane]);
            MSb[(wrow + 8 * i) * 36 + lane] = bfsplat(m);
        }
    }
    __syncthreads();

    // ---- stage Wh1 (bf16 col-pairs, warps 0-6) + MI (warp 7) ----
    if (wrow < 7) {
        for (int idx = tid; idx < 2048; idx += 224) {
            const float2 w = __ldg((const float2*)&Wh1[(idx >> 6) * 128 + 2 * (idx & 63)]);
            A[idx] = bf2(w.x, w.y);
        }
    } else {
        float s = 0.f;
        #pragma unroll 8
        for (int e = 0; e < 32; e++)
            s += maskv[e] * blo(MSb[e * 36 + lane]);
        MI[lane] = s;
    }
    __syncthreads();

    // ---- GEMM3: G1[32][128] = silu(MS @ Wh1 + bh1), bf16x2 over col pairs ----
    unsigned a3[4][2];
    #pragma unroll
    for (int i = 0; i < 4; i++) { a3[i][0] = 0u; a3[i][1] = 0u; }
    #pragma unroll 4
    for (int r = 0; r < 32; r++) {
        unsigned mv[4];
        #pragma unroll
        for (int i = 0; i < 4; i++) mv[i] = MSb[(wrow + 8 * i) * 36 + r];
        const unsigned w0 = A[r * 64 + lane * 2];
        const unsigned w1 = A[r * 64 + lane * 2 + 1];
        #pragma unroll
        for (int i = 0; i < 4; i++) {
            a3[i][0] = hfma2(mv[i], w0, a3[i][0]);
            a3[i][1] = hfma2(mv[i], w1, a3[i][1]);
        }
    }
    __syncthreads();   // A reads done; H1u reads long done -> G1u alias safe

    // ---- G1 write + stage Wh2 interleaved ----
    #pragma unroll
    for (int i = 0; i < 4; i++) {
        const int e = wrow + 8 * i;
        #pragma unroll
        for (int jj = 0; jj < 2; jj++) {
            const int c0 = 4 * lane + 2 * jj;
            const float g0 = siluf(blo(a3[i][jj]) + bh1[c0]);
            const float g1 = siluf(bhi(a3[i][jj]) + bh1[c0 + 1]);
            G1u[e * 68 + lane * 2 + jj] = bf2(g0, g1);
        }
    }
    for (int idx = tid; idx < 512; idx += 256) {
        const int c8 = idx >> 5, l = idx & 31;
        #pragma unroll
        for (int m = 0; m < 4; m++) {
            const int k = 8 * c8 + 2 * m;
            A[c8 * 128 + l * 4 + m] = bf2(__ldg(&Wh2[k * 32 + l]), __ldg(&Wh2[(k + 1) * 32 + l]));
        }
    }
    __syncthreads();

    // ---- GEMM4: WS[32][32] = G1 @ Wh2 + bh2, bf16x2 over K ----
    {
        unsigned a4[4] = {0u, 0u, 0u, 0u};
        const uint4* A4 = (const uint4*)A;
        const uint4* G4 = (const uint4*)G1u;   // row stride 17 uint4
        for (int c = 0; c < 16; c++) {
            const uint4 w = A4[c * 32 + lane];
            #pragma unroll
            for (int i = 0; i < 4; i++) {
                const uint4 g = G4[(wrow + 8 * i) * 17 + c];
                a4[i] = hfma2(g.x, w.x, a4[i]);
                a4[i] = hfma2(g.y, w.y, a4[i]);
                a4[i] = hfma2(g.z, w.z, a4[i]);
                a4[i] = hfma2(g.w, w.w, a4[i]);
            }
        }
        #pragma unroll
        for (int i = 0; i < 4; i++)
            WS[(wrow + 8 * i) * 36 + lane] = blo(a4[i]) + bhi(a4[i]) + bh2[lane];
    }
    __syncthreads();

    // ---- htype (warps 0-5, two edge-halves) + NI prep (warps 6-7) ----
    if (tid < 192) {
        const int half = (tid >= 96);
        const int t = tid - 96 * half;
        const int d = t / 3;
        const float hs = hns[d], hb = hnb[d];
        const float fi = f1i_s[t];
        const int e0 = half * 16;
        float s = 0.f;
        #pragma unroll 4
        for (int e = e0; e < e0 + 16; e++) {
            const float nrm  = EIc[e * 36 + d];
            const float coef = __fdividef(nrm * hs + hb, fmaxf(nrm, 1e-8f));
            const float relv = fi - __ldg(&f1[(size_t)(bbase + nbr_s[e]) * 96 + t]);
            s += relv * coef * WS[e * 36 + d];
        }
        HT2[tid] = s;
    } else if (tid < 256) {
        const int c = tid - 192;
        NI[c] = (nodes_s[c] - stats[0]) * stats[1] * lng[c] + lnb[c];
        if (c < 32) NI[64 + c] = MI[c];
    }
    __syncthreads();

    // ---- N1[128] = silu(node_in @ Wn1 + bn1) ----
    if (tid < 128) {
        float a = 0.f;
        #pragma unroll 8
        for (int r = 0; r < 96; r++) a += NI[r] * __ldg(&Wn1[r * 128 + tid]);
        N1s[tid] = siluf(a + bn1[tid]);
    }
    __syncthreads();

    // ---- node_out[64] = N1 @ Wn2 + bn2 + nodes ----
    if (tid < 64) {
        float a = 0.f;
        #pragma unroll 8
        for (int r = 0; r < 128; r++) a += N1s[r] * __ldg(&Wn2[r * 64 + tid]);
        const float v = a + bn2[tid] + nodes_s[tid];
        nouts[tid] = v;
        out[(size_t)node * 64 + tid] = v;
    }
    __syncthreads();

    // ---- gate[32] = sigmoid(node_out @ Wg + bg) ----
    if (tid < 32) {
        float a = 0.f;
        #pragma unroll 8
        for (int r = 0; r < 64; r++) a += nouts[r] * __ldg(&Wg[r * 32 + tid]);
        gates[tid] = sigmf(a + bg[tid]);
    }
    __syncthreads();

    // ---- f1_out = (features1 + htype_update) * gate ----
    if (tid < 96) {
        const int d = tid / 3;
        const float v = (f1i_s[tid] + HT2[tid] + HT2[96 + tid]) * gates[d];
        out[(size_t)Bb * Nn * D0 + (size_t)node * 96 + tid] = v;
    }
}

extern "C" void kernel_launch(void* const* d_in, const int* in_sizes, int n_in,
                              void* d_out, int out_size) {
    const float* f0   = (const float*)d_in[0];
    const float* f1   = (const float*)d_in[1];
    const int*   nbr  = (const int*)d_in[2];
    const unsigned char* msk = (const unsigned char*)d_in[3];
    const float* rdist= (const float*)d_in[4];
    const float* We1  = (const float*)d_in[5];
    const float* be1  = (const float*)d_in[6];
    const float* We2  = (const float*)d_in[7];
    const float* be2  = (const float*)d_in[8];
    const float* Wh1  = (const float*)d_in[9];
    const float* bh1  = (const float*)d_in[10];
    const float* Wh2  = (const float*)d_in[11];
    const float* bh2  = (const float*)d_in[12];
    const float* Wn1  = (const float*)d_in[13];
    const float* bn1  = (const float*)d_in[14];
    const float* Wn2  = (const float*)d_in[15];
    const float* bn2  = (const float*)d_in[16];
    const float* Wg   = (const float*)d_in[17];
    const float* bg   = (const float*)d_in[18];
    const float* lng  = (const float*)d_in[19];
    const float* lnb  = (const float*)d_in[20];
    const float* hns  = (const float*)d_in[21];
    const float* hnb  = (const float*)d_in[22];
    float* out = (float*)d_out;

    proj_kernel<<<NT / 16, 256>>>(f0, We1, be1);

    // smem: A 2688u32 + H1 5248u32 + EIc 1152f + EIb 1152u32 + PI 324f
    //       + MSb 1152u32 + WS 1152f + HT2..misc 770f  = 13638 words
    const size_t smem_bytes = 13638 * 4;

    cudaFuncSetAttribute(egnn_main, cudaFuncAttributeMaxDynamicSharedMemorySize,
                         (int)smem_bytes);

    egnn_main<<<NT, 256, smem_bytes>>>(
        f0, f1, nbr, msk, rdist, We1,
        We2, be2, Wh1, bh1, Wh2, bh2,
        Wn1, bn1, Wn2, bn2, Wg, bg, lng, lnb, hns, hnb, out);
}

// round 8
// speedup vs baseline: 2.0487x; 1.1691x over previous
#include <cuda_runtime.h>
#include <math.h>

#define Bb 2
#define Nn 4096
#define NT (Bb*Nn)
#define Kk 32
#define D0 64
#define E2C 322

typedef unsigned long long ull;

__device__ float PI_g[(size_t)NT * E2C + 384];
__device__ float PJ_g[(size_t)NT * E2C + 384];

__device__ __forceinline__ float siluf(float x) { return x / (1.f + __expf(-x)); }
__device__ __forceinline__ float sigmf(float x) { return 1.f / (1.f + __expf(-x)); }
__device__ __forceinline__ unsigned bf2(float lo, float hi) {
    unsigned r; asm("cvt.rn.bf16x2.f32 %0, %1, %2;" : "=r"(r) : "f"(hi), "f"(lo)); return r;
}
__device__ __forceinline__ unsigned bfsplat(float x) {
    unsigned r; asm("cvt.rn.bf16x2.f32 %0, %1, %1;" : "=r"(r) : "f"(x)); return r;
}
__device__ __forceinline__ unsigned hfma2(unsigned a, unsigned b, unsigned c) {
    unsigned d; asm("fma.rn.bf16x2 %0, %1, %2, %3;" : "=r"(d) : "r"(a), "r"(b), "r"(c)); return d;
}
__device__ __forceinline__ float blo(unsigned u) { return __uint_as_float(u << 16); }
__device__ __forceinline__ float bhi(unsigned u) { return __uint_as_float(u & 0xffff0000u); }
__device__ __forceinline__ ull pk2(float lo, float hi) {
    ull r; asm("mov.b64 %0, {%1, %2};" : "=l"(r) : "f"(lo), "f"(hi)); return r;
}
__device__ __forceinline__ void up2(ull v, float& lo, float& hi) {
    asm("mov.b64 {%0, %1}, %2;" : "=f"(lo), "=f"(hi) : "l"(v));
}
__device__ __forceinline__ ull ffma2(ull a, ull b, ull c) {
    ull d; asm("fma.rn.f32x2 %0, %1, %2, %3;" : "=l"(d) : "l"(a), "l"(b), "l"(c)); return d;
}

// ---------------- per-node projections: 8 nodes/block, register-reuse GEMM
// PI = nodes @ We1[0:64] + be1,  PJ = nodes @ We1[64:128]
__global__ void __launch_bounds__(192)
proj_kernel(const float* __restrict__ f0, const float* __restrict__ We1,
            const float* __restrict__ be1)
{
    __shared__ ull ndu[8][64];   // f32x2 splat node features
    const int nb = blockIdx.x * 8;
    const int tid = threadIdx.x;
    for (int idx = tid; idx < 512; idx += 192) {
        const float v = f0[(size_t)nb * 64 + idx];
        ndu[idx >> 6][idx & 63] = pk2(v, v);
    }
    __syncthreads();
    const int p = tid;       // column pair 0..160
    if (p < 161) {
        ull si[8], sj[8];
        #pragma unroll
        for (int n = 0; n < 8; n++) { si[n] = 0ull; sj[n] = 0ull; }
        for (int d = 0; d < 64; d++) {
            const float2 wi = __ldg((const float2*)&We1[(size_t)d * E2C + 2 * p]);
            const float2 wj = __ldg((const float2*)&We1[(size_t)(64 + d) * E2C + 2 * p]);
            const ull wiu = pk2(wi.x, wi.y);
            const ull wju = pk2(wj.x, wj.y);
            #pragma unroll
            for (int n = 0; n < 8; n++) {
                const ull v = ndu[n][d];
                si[n] = ffma2(v, wiu, si[n]);
                sj[n] = ffma2(v, wju, sj[n]);
            }
        }
        const float2 b = *(const float2*)&be1[2 * p];
        #pragma unroll
        for (int n = 0; n < 8; n++) {
            float a0, a1, c0, c1;
            up2(si[n], a0, a1); up2(sj[n], c0, c1);
            *(float2*)&PI_g[(size_t)(nb + n) * E2C + 2 * p] = make_float2(a0 + b.x, a1 + b.y);
            *(float2*)&PJ_g[(size_t)(nb + n) * E2C + 2 * p] = make_float2(c0, c1);
        }
    }
}

// ---------------- main fused kernel: bf16x2 edge GEMMs, transposed edge arrays
__global__ void __launch_bounds__(256, 4)
egnn_main(const float* __restrict__ f0, const float* __restrict__ f1,
          const int* __restrict__ nbr, const unsigned char* __restrict__ msk,
          const float* __restrict__ rdist,
          const float* __restrict__ We1,
          const float* __restrict__ We2, const float* __restrict__ be2,
          const float* __restrict__ Wh1, const float* __restrict__ bh1,
          const float* __restrict__ Wh2, const float* __restrict__ bh2,
          const float* __restrict__ Wn1, const float* __restrict__ bn1,
          const float* __restrict__ Wn2, const float* __restrict__ bn2,
          const float* __restrict__ Wg,  const float* __restrict__ bg,
          const float* __restrict__ lng, const float* __restrict__ lnb,
          const float* __restrict__ hns, const float* __restrict__ hnb,
          float* __restrict__ out)
{
    extern __shared__ float sm[];
    unsigned* A    = (unsigned*)sm;            // 2688 u32: rotating bf16 weight stage
    unsigned* H1u  = A + 2688;                 // [32 e][164] u32 bf16-pairs; aliased by G1u
    float*    EIcT = (float*)(H1u + 5248);     // [32 d][36] rel_norm fp32 (transposed)
    unsigned* EIbT = (unsigned*)(EIcT + 1152); // [33 k][36] splat bf16x2 (transposed)
    float*    PI   = (float*)(EIbT + 1188);    // [324]
    unsigned* MSbT = (unsigned*)(PI + 324);    // [32 r][36] m_ij splat bf16x2 (transposed)
    float*    WST  = (float*)(MSbT + 1152);    // [32 d][36] w fp32 (transposed)
    float*    HT2  = WST + 1152;               // [192]
    float*    nodes_s = HT2 + 192;             // [64]
    float*    f1i_s   = nodes_s + 64;          // [96]
    float*    MI   = f1i_s + 96;               // [32]
    float*    NI   = MI + 32;                  // [96]
    float*    N1s  = NI + 96;                  // [128]
    float*    nouts= N1s + 128;                // [64]
    float*    gates= nouts + 64;               // [32]
    float*    maskv= gates + 32;               // [32]
    float*    stats= maskv + 32;               // [2]
    int*      nbr_s= (int*)(stats + 2);        // [32]
    unsigned* G1u  = H1u;                      // alias: [32 e][68] u32

    const int tid  = threadIdx.x;
    const int lane = tid & 31;
    const int wrow = tid >> 5;
    const int node = blockIdx.x;
    const int bbase = (node / Nn) * Nn;

    // ---- P0: node features, per-edge scalars, PI, GEMM1 weight stage 0 ----
    if (tid < 64)           nodes_s[tid]    = f0[(size_t)node * 64 + tid];
    else if (tid < 160)     f1i_s[tid - 64] = f1[(size_t)node * 96 + (tid - 64)];
    if (tid < 32)           nbr_s[tid] = nbr[node * Kk + tid];
    else if (tid < 64)      maskv[tid - 32] = (float)msk[node * Kk + tid - 32];
    else if (tid < 96)      EIbT[32 * 36 + (tid - 64)] = bfsplat(rdist[node * Kk + tid - 64]);
    for (int c = tid; c < 324; c += 256)
        PI[c] = (c < E2C) ? PI_g[(size_t)node * E2C + c] : 0.f;
    for (int idx = tid; idx < 11 * 192; idx += 256) {
        const int kr = idx / 192, p = idx - kr * 192;
        unsigned v = 0u;
        if (p < 161) {
            const float2 w = __ldg((const float2*)&We1[(size_t)(128 + kr) * E2C + 2 * p]);
            v = bf2(w.x, w.y);
        }
        A[idx] = v;
    }
    __syncthreads();

    // ---- P1: rel_norm gather (e=wrow+8i, d=lane) + LN stats ----
    #pragma unroll
    for (int i = 0; i < 4; i++) {
        const int e = wrow + 8 * i;
        const float* f1j = f1 + (size_t)(bbase + nbr_s[e]) * 96;
        const float r0 = f1i_s[lane * 3 + 0] - f1j[lane * 3 + 0];
        const float r1 = f1i_s[lane * 3 + 1] - f1j[lane * 3 + 1];
        const float r2 = f1i_s[lane * 3 + 2] - f1j[lane * 3 + 2];
        const float nrm = sqrtf(r0 * r0 + r1 * r1 + r2 * r2);
        EIcT[lane * 36 + e] = nrm;
        EIbT[lane * 36 + e] = bfsplat(nrm);
    }
    if (wrow == 7) {
        float x0 = nodes_s[lane], x1 = nodes_s[lane + 32];
        float s = x0 + x1, ss = x0 * x0 + x1 * x1;
        #pragma unroll
        for (int o = 16; o > 0; o >>= 1) {
            s  += __shfl_down_sync(0xffffffffu, s,  o);
            ss += __shfl_down_sync(0xffffffffu, ss, o);
        }
        if (lane == 0) {
            const float mu  = s * (1.f / 64.f);
            const float var = ss * (1.f / 64.f) - mu * mu;
            stats[0] = mu;
            stats[1] = rsqrtf(var + 1e-5f);
        }
    }
    __syncthreads();

    // ---- GEMM1 (K=33, 3 staged chunks; thread = edges 4*wrow..+3 x cols lane+32jj) ----
    unsigned acc2[4][6];
    #pragma unroll
    for (int i = 0; i < 4; i++)
        #pragma unroll
        for (int jj = 0; jj < 6; jj++) acc2[i][jj] = 0u;

    #pragma unroll
    for (int s = 0; s < 3; s++) {
        for (int kr = 0; kr < 11; kr++) {
            const int k = 11 * s + kr;
            const uint4 ev4 = *(const uint4*)&EIbT[k * 36 + 4 * wrow];   // broadcast LDS.128
            #pragma unroll
            for (int jj = 0; jj < 6; jj++) {
                const unsigned w = A[kr * 192 + lane + 32 * jj];
                acc2[0][jj] = hfma2(ev4.x, w, acc2[0][jj]);
                acc2[1][jj] = hfma2(ev4.y, w, acc2[1][jj]);
                acc2[2][jj] = hfma2(ev4.z, w, acc2[2][jj]);
                acc2[3][jj] = hfma2(ev4.w, w, acc2[3][jj]);
            }
        }
        __syncthreads();
        if (s < 2) {
            for (int idx = tid; idx < 11 * 192; idx += 256) {
                const int kr = idx / 192, p = idx - kr * 192;
                unsigned v = 0u;
                if (p < 161) {
                    const float2 w = __ldg((const float2*)&We1[(size_t)(128 + 11 * (s + 1) + kr) * E2C + 2 * p]);
                    v = bf2(w.x, w.y);
                }
                A[idx] = v;
            }
            __syncthreads();
        }
    }

    // ---- epilogue: H1 = bf16(silu(acc + PI + PJ)), overlap We2 chunk-0 staging ----
    #pragma unroll
    for (int i = 0; i < 4; i++) {
        const int e = 4 * wrow + i;
        const float* pj = PJ_g + (size_t)(bbase + nbr_s[e]) * E2C;
        #pragma unroll
        for (int jj = 0; jj < 6; jj++) {
            const int p = lane + 32 * jj;
            if (p < 161) {
                const float2 pi2 = *(const float2*)&PI[2 * p];
                const float2 pj2 = __ldg((const float2*)(pj + 2 * p));
                const float h0 = siluf(blo(acc2[i][jj]) + pi2.x + pj2.x);
                const float h1 = siluf(bhi(acc2[i][jj]) + pi2.y + pj2.y);
                H1u[e * 164 + p] = bf2(h0, h1);
            }
        }
    }
    if (tid < 96) H1u[(tid / 3) * 164 + 161 + (tid % 3)] = 0u;   // zero K-pad
    // stage We2 groups 0..20: vector row-pair loads
    for (int idx = tid; idx < 21 * 32; idx += 256) {
        const int c8 = idx >> 5, r = idx & 31;
        const int m = r >> 3, q = r & 7;
        const int k = 8 * c8 + 2 * m;
        const float4 w0 = __ldg((const float4*)&We2[k * 32 + 4 * q]);
        const float4 w1 = __ldg((const float4*)&We2[(k + 1) * 32 + 4 * q]);
        A[c8 * 128 + (4 * q + 0) * 4 + m] = bf2(w0.x, w1.x);
        A[c8 * 128 + (4 * q + 1) * 4 + m] = bf2(w0.y, w1.y);
        A[c8 * 128 + (4 * q + 2) * 4 + m] = bf2(w0.z, w1.z);
        A[c8 * 128 + (4 * q + 3) * 4 + m] = bf2(w0.w, w1.w);
    }
    __syncthreads();

    // ---- GEMM2 (K=328 incl pad, bf16x2 over K, chunks 21 + 20) ----
    {
        unsigned a2[4] = {0u, 0u, 0u, 0u};
        const uint4* A4 = (const uint4*)A;
        const uint4* H4 = (const uint4*)H1u;   // row stride 41 uint4
        for (int c = 0; c < 21; c++) {
            const uint4 w = A4[c * 32 + lane];
            #pragma unroll
            for (int i = 0; i < 4; i++) {
                const uint4 h = H4[(4 * wrow + i) * 41 + c];
                a2[i] = hfma2(h.x, w.x, a2[i]);
                a2[i] = hfma2(h.y, w.y, a2[i]);
                a2[i] = hfma2(h.z, w.z, a2[i]);
                a2[i] = hfma2(h.w, w.w, a2[i]);
            }
        }
        __syncthreads();
        for (int idx = tid; idx < 20 * 32; idx += 256) {
            const int c8 = idx >> 5, r = idx & 31;
            const int m = r >> 3, q = r & 7;
            const int k = 8 * (21 + c8) + 2 * m;
            float4 w0 = make_float4(0.f, 0.f, 0.f, 0.f), w1 = w0;
            if (k     < E2C) w0 = __ldg((const float4*)&We2[k * 32 + 4 * q]);
            if (k + 1 < E2C) w1 = __ldg((const float4*)&We2[(k + 1) * 32 + 4 * q]);
            A[c8 * 128 + (4 * q + 0) * 4 + m] = bf2(w0.x, w1.x);
            A[c8 * 128 + (4 * q + 1) * 4 + m] = bf2(w0.y, w1.y);
            A[c8 * 128 + (4 * q + 2) * 4 + m] = bf2(w0.z, w1.z);
            A[c8 * 128 + (4 * q + 3) * 4 + m] = bf2(w0.w, w1.w);
        }
        __syncthreads();
        for (int c = 0; c < 20; c++) {
            const uint4 w = A4[c * 32 + lane];
            #pragma unroll
            for (int i = 0; i < 4; i++) {
                const uint4 h = H4[(4 * wrow + i) * 41 + 21 + c];
                a2[i] = hfma2(h.x, w.x, a2[i]);
                a2[i] = hfma2(h.y, w.y, a2[i]);
                a2[i] = hfma2(h.z, w.z, a2[i]);
                a2[i] = hfma2(h.w, w.w, a2[i]);
            }
        }
        #pragma unroll
        for (int i = 0; i < 4; i++) {
            const float m = siluf(blo(a2[i]) + bhi(a2[i]) + be2[lane]);
            MSbT[lane * 36 + 4 * wrow + i] = bfsplat(m);
        }
    }
    __syncthreads();

    // ---- stage Wh1 (warps 0-6) + MI (warp 7) ----
    if (wrow < 7) {
        for (int idx = tid; idx < 1024; idx += 224) {
            const float4 w = __ldg((const float4*)&Wh1[(idx >> 5) * 128 + 4 * (idx & 31)]);
            A[2 * idx]     = bf2(w.x, w.y);
            A[2 * idx + 1] = bf2(w.z, w.w);
        }
    } else {
        float s = 0.f;
        #pragma unroll 8
        for (int e = 0; e < 32; e++)
            s += maskv[e] * blo(MSbT[lane * 36 + e]);
        MI[lane] = s;
    }
    __syncthreads();

    // ---- GEMM3: G1[32][128] = silu(MS @ Wh1 + bh1) ----
    unsigned a3[4][2];
    #pragma unroll
    for (int i = 0; i < 4; i++) { a3[i][0] = 0u; a3[i][1] = 0u; }
    #pragma unroll 4
    for (int r = 0; r < 32; r++) {
        const uint4 mv4 = *(const uint4*)&MSbT[r * 36 + 4 * wrow];   // broadcast LDS.128
        const unsigned w0 = A[r * 64 + lane * 2];
        const unsigned w1 = A[r * 64 + lane * 2 + 1];
        a3[0][0] = hfma2(mv4.x, w0, a3[0][0]); a3[0][1] = hfma2(mv4.x, w1, a3[0][1]);
        a3[1][0] = hfma2(mv4.y, w0, a3[1][0]); a3[1][1] = hfma2(mv4.y, w1, a3[1][1]);
        a3[2][0] = hfma2(mv4.z, w0, a3[2][0]); a3[2][1] = hfma2(mv4.z, w1, a3[2][1]);
        a3[3][0] = hfma2(mv4.w, w0, a3[3][0]); a3[3][1] = hfma2(mv4.w, w1, a3[3][1]);
    }
    __syncthreads();   // A reads done; H1u reads long done -> G1u alias safe

    // ---- G1 write + stage Wh2 ----
    #pragma unroll
    for (int i = 0; i < 4; i++) {
        const int e = 4 * wrow + i;
        #pragma unroll
        for (int jj = 0; jj < 2; jj++) {
            const int c0 = 4 * lane + 2 * jj;
            const float g0 = siluf(blo(a3[i][jj]) + bh1[c0]);
            const float g1 = siluf(bhi(a3[i][jj]) + bh1[c0 + 1]);
            G1u[e * 68 + lane * 2 + jj] = bf2(g0, g1);
        }
    }
    for (int idx = tid; idx < 512; idx += 256) {
        const int c8 = idx >> 5, r = idx & 31;
        const int m = r >> 3, q = r & 7;
        const int k = 8 * c8 + 2 * m;
        const float4 w0 = __ldg((const float4*)&Wh2[k * 32 + 4 * q]);
        const float4 w1 = __ldg((const float4*)&Wh2[(k + 1) * 32 + 4 * q]);
        A[c8 * 128 + (4 * q + 0) * 4 + m] = bf2(w0.x, w1.x);
        A[c8 * 128 + (4 * q + 1) * 4 + m] = bf2(w0.y, w1.y);
        A[c8 * 128 + (4 * q + 2) * 4 + m] = bf2(w0.z, w1.z);
        A[c8 * 128 + (4 * q + 3) * 4 + m] = bf2(w0.w, w1.w);
    }
    __syncthreads();

    // ---- GEMM4: WS[32][32] = G1 @ Wh2 + bh2 ----
    {
        unsigned a4[4] = {0u, 0u, 0u, 0u};
        const uint4* A4 = (const uint4*)A;
        const uint4* G4 = (const uint4*)G1u;   // row stride 17 uint4
        for (int c = 0; c < 16; c++) {
            const uint4 w = A4[c * 32 + lane];
            #pragma unroll
            for (int i = 0; i < 4; i++) {
                const uint4 g = G4[(4 * wrow + i) * 17 + c];
                a4[i] = hfma2(g.x, w.x, a4[i]);
                a4[i] = hfma2(g.y, w.y, a4[i]);
                a4[i] = hfma2(g.z, w.z, a4[i]);
                a4[i] = hfma2(g.w, w.w, a4[i]);
            }
        }
        #pragma unroll
        for (int i = 0; i < 4; i++)
            WST[lane * 36 + 4 * wrow + i] = blo(a4[i]) + bhi(a4[i]) + bh2[lane];
    }
    __syncthreads();

    // ---- htype (warps 0-5, vectorized over e) + NI prep (warps 6-7) ----
    if (tid < 192) {
        const int half = (tid >= 96);
        const int t = tid - 96 * half;
        const int d = t / 3;
        const float hs = hns[d], hb = hnb[d];
        const float fi = f1i_s[t];
        const int e0 = half * 16;
        float s = 0.f;
        #pragma unroll
        for (int e4 = 0; e4 < 4; e4++) {
            const float4 nrm4 = *(const float4*)&EIcT[d * 36 + e0 + 4 * e4];
            const float4 w4   = *(const float4*)&WST[d * 36 + e0 + 4 * e4];
            #pragma unroll
            for (int m = 0; m < 4; m++) {
                const int e = e0 + 4 * e4 + m;
                const float nrm = (m == 0) ? nrm4.x : (m == 1) ? nrm4.y : (m == 2) ? nrm4.z : nrm4.w;
                const float wv  = (m == 0) ? w4.x   : (m == 1) ? w4.y   : (m == 2) ? w4.z   : w4.w;
                const float coef = __fdividef(nrm * hs + hb, fmaxf(nrm, 1e-8f));
                const float relv = fi - __ldg(&f1[(size_t)(bbase + nbr_s[e]) * 96 + t]);
                s += relv * coef * wv;
            }
        }
        HT2[tid] = s;
    } else if (tid < 256) {
        const int c = tid - 192;
        NI[c] = (nodes_s[c] - stats[0]) * stats[1] * lng[c] + lnb[c];
        if (c < 32) NI[64 + c] = MI[c];
    }
    __syncthreads();

    // ---- N1[128] = silu(node_in @ Wn1 + bn1) ----
    if (tid < 128) {
        float a = 0.f;
        #pragma unroll 8
        for (int r = 0; r < 96; r++) a += NI[r] * __ldg(&Wn1[r * 128 + tid]);
        N1s[tid] = siluf(a + bn1[tid]);
    }
    __syncthreads();

    // ---- node_out[64] = N1 @ Wn2 + bn2 + nodes ----
    if (tid < 64) {
        float a = 0.f;
        #pragma unroll 8
        for (int r = 0; r < 128; r++) a += N1s[r] * __ldg(&Wn2[r * 64 + tid]);
        const float v = a + bn2[tid] + nodes_s[tid];
        nouts[tid] = v;
        out[(size_t)node * 64 + tid] = v;
    }
    __syncthreads();

    // ---- gate[32] = sigmoid(node_out @ Wg + bg) ----
    if (tid < 32) {
        float a = 0.f;
        #pragma unroll 8
        for (int r = 0; r < 64; r++) a += nouts[r] * __ldg(&Wg[r * 32 + tid]);
        gates[tid] = sigmf(a + bg[tid]);
    }
    __syncthreads();

    // ---- f1_out = (features1 + htype_update) * gate ----
    if (tid < 96) {
        const int d = tid / 3;
        const float v = (f1i_s[tid] + HT2[tid] + HT2[96 + tid]) * gates[d];
        out[(size_t)Bb * Nn * D0 + (size_t)node * 96 + tid] = v;
    }
}

extern "C" void kernel_launch(void* const* d_in, const int* in_sizes, int n_in,
                              void* d_out, int out_size) {
    const float* f0   = (const float*)d_in[0];
    const float* f1   = (const float*)d_in[1];
    const int*   nbr  = (const int*)d_in[2];
    const unsigned char* msk = (const unsigned char*)d_in[3];
    const float* rdist= (const float*)d_in[4];
    const float* We1  = (const float*)d_in[5];
    const float* be1  = (const float*)d_in[6];
    const float* We2  = (const float*)d_in[7];
    const float* be2  = (const float*)d_in[8];
    const float* Wh1  = (const float*)d_in[9];
    const float* bh1  = (const float*)d_in[10];
    const float* Wh2  = (const float*)d_in[11];
    const float* bh2  = (const float*)d_in[12];
    const float* Wn1  = (const float*)d_in[13];
    const float* bn1  = (const float*)d_in[14];
    const float* Wn2  = (const float*)d_in[15];
    const float* bn2  = (const float*)d_in[16];
    const float* Wg   = (const float*)d_in[17];
    const float* bg   = (const float*)d_in[18];
    const float* lng  = (const float*)d_in[19];
    const float* lnb  = (const float*)d_in[20];
    const float* hns  = (const float*)d_in[21];
    const float* hnb  = (const float*)d_in[22];
    float* out = (float*)d_out;

    proj_kernel<<<NT / 8, 192>>>(f0, We1, be1);

    // words: A 2688 + H1u 5248 + EIcT 1152 + EIbT 1188 + PI 324 + MSbT 1152
    //        + WST 1152 + HT2 192 + misc 578  = 13674
    const size_t smem_bytes = 13674 * 4;

    cudaFuncSetAttribute(egnn_main, cudaFuncAttributeMaxDynamicSharedMemorySize,
                         (int)smem_bytes);

    egnn_main<<<NT, 256, smem_bytes>>>(
        f0, f1, nbr, msk, rdist, We1,
        We2, be2, Wh1, bh1, Wh2, bh2,
        Wn1, bn1, Wn2, bn2, Wg, bg, lng, lnb, hns, hnb, out);
}